// round 17
// baseline (speedup 1.0000x reference)
#include <cuda_runtime.h>
#include <cstdint>

// out[b,c] = dot(x[b,c,:HW], weight[c,:HW]) + bias[c]
// B = 512, C = 512, HW = 784 (float32). HBM-streaming bound, minimal traffic.
// R17 = R12 (aligned 2-row-pair 64-thr blocks, .cg x loads, __ldg weights,
// peeled tail, regs<=32, row-ordered grid) + SOFTWARE L2 PREFETCH one wave
// ahead: each CTA prefetches the 49-line x window of CTA bid+4736 (one full
// resident wave ahead). This decouples the DRAM fill stream from warp
// scheduling (demand loads inherit every scheduler hiccup); the consuming
// wave hits L2. One wave of prefetch = ~29 MB << 126 MB L2.

#define B_DIM 512
#define C_DIM 512
#define HW_DIM 784
#define HW_VEC4 (HW_DIM / 4)          // 196 float4 per row
#define PAIR_VEC4 (2 * HW_VEC4)       // 392 float4 per row-pair
#define PAIR_BYTES (PAIR_VEC4 * 16)   // 6272 B = 49 x 128B lines
#define PAIR_LINES 49
#define TOTAL_ROWS (B_DIM * C_DIM)    // 262144
#define WAVE_CTAS (148 * 32)          // 4736 CTAs resident per wave

// 128-bit load, L1-bypass (cache-global: L2 only)
__device__ __forceinline__ float4 ldg128_cg(const float4* p) {
    float4 v;
    asm volatile("ld.global.cg.v4.f32 {%0,%1,%2,%3}, [%4];"
                 : "=f"(v.x), "=f"(v.y), "=f"(v.z), "=f"(v.w)
                 : "l"(p));
    return v;
}

__device__ __forceinline__ void prefetch_l2(const void* p) {
    asm volatile("prefetch.global.L2 [%0];" :: "l"(p));
}

__global__ __launch_bounds__(64, 32) void scalar_mapping_kernel(
    const float* __restrict__ x,
    const float* __restrict__ weight,
    const float* __restrict__ bias,
    float* __restrict__ out)
{
    __shared__ float part[4];   // {w0.s0, w0.s1, w1.s0, w1.s1}

    const int tid  = threadIdx.x;        // 0..63
    const int lane = tid & 31;
    const int wid  = tid >> 5;           // 0 or 1

    const int r0 = blockIdx.x * 2;       // even row
    const int c0 = r0 & (C_DIM - 1);     // even -> c1 = c0+1 never wraps
    const int c1 = c0 + 1;

    // ---- Prefetch the x window of the CTA one wave ahead (fire-and-forget).
    {
        const int bpf = blockIdx.x + WAVE_CTAS;
        if (bpf < TOTAL_ROWS / 2 && tid < PAIR_LINES) {
            const char* pf = reinterpret_cast<const char*>(x)
                           + (size_t)bpf * PAIR_BYTES + (size_t)tid * 128;
            prefetch_l2(pf);
        }
    }

    // Contiguous, 128B-aligned 2-row window of x (6272 B = 49 lines).
    const float4* __restrict__ xr =
        reinterpret_cast<const float4*>(x + (size_t)r0 * HW_DIM);
    const float4* __restrict__ w0 =
        reinterpret_cast<const float4*>(weight + (size_t)c0 * HW_DIM);
    const float4* __restrict__ w1 =
        reinterpret_cast<const float4*>(weight + (size_t)c1 * HW_DIM);

    float s0 = 0.0f, s1 = 0.0f;

    // 6 full iterations: f = tid + 64*i in [0, 384) -- predicate-free.
    #pragma unroll
    for (int i = 0; i < 6; ++i) {
        const int f = tid + i * 64;
        const float4 xv = ldg128_cg(&xr[f]);       // L2 hit (prefetched)
        if (f < HW_VEC4) {
            const float4 wv = __ldg(&w0[f]);       // L1-resident weight
            s0 = fmaf(xv.x, wv.x, s0);
            s0 = fmaf(xv.y, wv.y, s0);
            s0 = fmaf(xv.z, wv.z, s0);
            s0 = fmaf(xv.w, wv.w, s0);
        } else {
            const float4 wv = __ldg(&w1[f - HW_VEC4]);
            s1 = fmaf(xv.x, wv.x, s1);
            s1 = fmaf(xv.y, wv.y, s1);
            s1 = fmaf(xv.z, wv.z, s1);
            s1 = fmaf(xv.w, wv.w, s1);
        }
    }
    // Peeled tail: f = 384 + tid, valid for tid < 8 (all in row 1).
    if (tid < 8) {
        const int f = 384 + tid;
        const float4 xv = ldg128_cg(&xr[f]);
        const float4 wv = __ldg(&w1[f - HW_VEC4]);
        s1 = fmaf(xv.x, wv.x, s1);
        s1 = fmaf(xv.y, wv.y, s1);
        s1 = fmaf(xv.z, wv.z, s1);
        s1 = fmaf(xv.w, wv.w, s1);
    }

    // Warp-level butterfly reduce of both accumulators.
    #pragma unroll
    for (int off = 16; off > 0; off >>= 1) {
        s0 += __shfl_xor_sync(0xFFFFFFFFu, s0, off);
        s1 += __shfl_xor_sync(0xFFFFFFFFu, s1, off);
    }

    if (lane == 0) {
        part[wid * 2 + 0] = s0;
        part[wid * 2 + 1] = s1;
    }
    __syncthreads();

    if (tid == 0) {
        float2 o;
        o.x = part[0] + part[2] + __ldg(&bias[c0]);
        o.y = part[1] + part[3] + __ldg(&bias[c1]);
        *reinterpret_cast<float2*>(&out[r0]) = o;   // 8B-aligned at even rows
    }
}

extern "C" void kernel_launch(void* const* d_in, const int* in_sizes, int n_in,
                              void* d_out, int out_size)
{
    const float* x      = (const float*)d_in[0];
    const float* weight = (const float*)d_in[1];
    const float* bias   = (const float*)d_in[2];
    float* out          = (float*)d_out;

    // One aligned 2-row pair per 64-thread block -> 131072 blocks in row order.
    const int blocks = TOTAL_ROWS / 2;

    scalar_mapping_kernel<<<blocks, 64>>>(x, weight, bias, out);
}